// round 3
// baseline (speedup 1.0000x reference)
#include <cuda_runtime.h>
#include <cstdint>

#define N_ROWS 8192
#define F_COLS 8192
#define K_SEL  2867u
#define WORDS_PER_ROW 256   /* 8192 / 32 */

// Scratch (static __device__ arrays — allocation-free per harness rules)
__device__ __align__(16) float g_boost[F_COLS];
__device__ __align__(16) float g_rboost[F_COLS];
// Transposed mask: g_mask[wordcol * N_ROWS + row]
__device__ unsigned g_mask[WORDS_PER_ROW * N_ROWS];

// ---------------------------------------------------------------------------
// Kernel 1: boost = exp(BETA*(target - duty_cycle)), and its reciprocal
// ---------------------------------------------------------------------------
__global__ void boost_kernel(const float* __restrict__ dc) {
    int j = blockIdx.x * blockDim.x + threadIdx.x;
    if (j < F_COLS) {
        const float target = 2867.0f / 8192.0f;   // exact dyadic
        float b = expf(1.5f * (target - dc[j]));
        g_boost[j]  = b;
        g_rboost[j] = 1.0f / b;
    }
}

// ---------------------------------------------------------------------------
// Radix-select helper: find bin B such that
//   count(keys in bins > B) < kr <= count(keys in bins >= B)
// over a 2048-bin histogram. Warp 0 performs the hierarchical scan.
// ---------------------------------------------------------------------------
__device__ __forceinline__ void select_bin(const unsigned* __restrict__ hist,
                                           unsigned* __restrict__ part,
                                           unsigned kr,
                                           volatile unsigned* sh_bin,
                                           volatile unsigned* sh_kr) {
    int t = threadIdx.x;
    // level 1: 256 partials of 8 bins each
    unsigned s = 0;
#pragma unroll
    for (int i = 0; i < 8; ++i) s += hist[t * 8 + i];
    part[t] = s;
    __syncthreads();

    if (t < 32) {
        // level 2: each lane sums 8 partials (64 bins per lane)
        unsigned c = 0;
#pragma unroll
        for (int i = 0; i < 8; ++i) c += part[t * 8 + i];
        // inclusive suffix sum across lanes (lane l -> count of bins >= l*64)
        unsigned v = c;
#pragma unroll
        for (int off = 1; off < 32; off <<= 1) {
            unsigned u = __shfl_down_sync(0xffffffffu, v, off);
            if (t + off < 32) v += u;
        }
        unsigned ab = __shfl_down_sync(0xffffffffu, v, 1);  // suffix of lane+1
        if (t == 31) ab = 0;
        unsigned m = __ballot_sync(0xffffffffu, v >= kr);
        int L = 31 - __clz(m);   // highest lane whose suffix still >= kr
        if (t == L) {
            unsigned cum = ab;   // keys strictly above this lane's bin range
            int bin = 0; unsigned krn = 1;
            for (int g = 7; g >= 0; --g) {       // groups descending
                int gi = L * 8 + g;
                unsigned pg = part[gi];
                if (cum + pg >= kr) {
                    for (int b = 7; b >= 0; --b) {  // bins descending
                        int bi = gi * 8 + b;
                        unsigned hb = hist[bi];
                        if (cum + hb >= kr) { bin = bi; krn = kr - cum; break; }
                        cum += hb;
                    }
                    break;
                }
                cum += pg;
            }
            *sh_bin = (unsigned)bin;
            *sh_kr  = krn;
        }
    }
    __syncthreads();
}

// ---------------------------------------------------------------------------
// Kernel 2: one CTA per row. Keys of boosted values live in smem; 3-pass
// radix select (11+11+10 bits) finds the k-th largest; output pass writes
// thresholded values (reconstructed from the key) + positivity bitmasks.
// ---------------------------------------------------------------------------
__global__ __launch_bounds__(256)
void topk_kernel(const float* __restrict__ in, float* __restrict__ out) {
    extern __shared__ unsigned smem[];
    unsigned* keys = smem;                 // 8192
    unsigned* hist = smem + 8192;          // 2048
    unsigned* part = smem + 8192 + 2048;   // 256
    __shared__ unsigned sh_bin, sh_kr;

    const int t = threadIdx.x;
    const int row = blockIdx.x;

    for (int i = t; i < 2048; i += 256) hist[i] = 0;
    __syncthreads();

    // ---- load pass: read row, form monotonic keys, pass-1 hist (bits 31..21)
    const float4* __restrict__ rowp =
        reinterpret_cast<const float4*>(in) + (size_t)row * (F_COLS / 4);
    const float4* __restrict__ bp = reinterpret_cast<const float4*>(g_boost);
#pragma unroll
    for (int it = 0; it < 8; ++it) {
        int i4 = it * 256 + t;
        float4 v = rowp[i4];
        float4 b = bp[i4];
        float f0 = v.x * b.x, f1 = v.y * b.y, f2 = v.z * b.z, f3 = v.w * b.w;
        unsigned u0 = __float_as_uint(f0), u1 = __float_as_uint(f1);
        unsigned u2 = __float_as_uint(f2), u3 = __float_as_uint(f3);
        unsigned k0 = (u0 & 0x80000000u) ? ~u0 : (u0 | 0x80000000u);
        unsigned k1 = (u1 & 0x80000000u) ? ~u1 : (u1 | 0x80000000u);
        unsigned k2 = (u2 & 0x80000000u) ? ~u2 : (u2 | 0x80000000u);
        unsigned k3 = (u3 & 0x80000000u) ? ~u3 : (u3 | 0x80000000u);
        reinterpret_cast<uint4*>(keys)[i4] = make_uint4(k0, k1, k2, k3);
        atomicAdd(&hist[k0 >> 21], 1u);
        atomicAdd(&hist[k1 >> 21], 1u);
        atomicAdd(&hist[k2 >> 21], 1u);
        atomicAdd(&hist[k3 >> 21], 1u);
    }
    __syncthreads();

    // ---- select pass 1 (bits 31..21)
    select_bin(hist, part, K_SEL, &sh_bin, &sh_kr);
    unsigned B1 = sh_bin, kr2 = sh_kr;

    // ---- pass 2 histogram (bits 20..10) over keys matching B1
    for (int i = t; i < 2048; i += 256) hist[i] = 0;
    __syncthreads();
#pragma unroll
    for (int it = 0; it < 8; ++it) {
        uint4 kk = reinterpret_cast<const uint4*>(keys)[it * 256 + t];
        if ((kk.x >> 21) == B1) atomicAdd(&hist[(kk.x >> 10) & 0x7FFu], 1u);
        if ((kk.y >> 21) == B1) atomicAdd(&hist[(kk.y >> 10) & 0x7FFu], 1u);
        if ((kk.z >> 21) == B1) atomicAdd(&hist[(kk.z >> 10) & 0x7FFu], 1u);
        if ((kk.w >> 21) == B1) atomicAdd(&hist[(kk.w >> 10) & 0x7FFu], 1u);
    }
    __syncthreads();
    select_bin(hist, part, kr2, &sh_bin, &sh_kr);
    unsigned B2 = sh_bin, kr3 = sh_kr;

    // ---- pass 3 histogram (bits 9..0) over keys matching (B1,B2)
    for (int i = t; i < 2048; i += 256) hist[i] = 0;
    __syncthreads();
    const unsigned pref = (B1 << 11) | B2;
#pragma unroll
    for (int it = 0; it < 8; ++it) {
        uint4 kk = reinterpret_cast<const uint4*>(keys)[it * 256 + t];
        if ((kk.x >> 10) == pref) atomicAdd(&hist[kk.x & 0x3FFu], 1u);
        if ((kk.y >> 10) == pref) atomicAdd(&hist[kk.y & 0x3FFu], 1u);
        if ((kk.z >> 10) == pref) atomicAdd(&hist[kk.z & 0x3FFu], 1u);
        if ((kk.w >> 10) == pref) atomicAdd(&hist[kk.w & 0x3FFu], 1u);
    }
    __syncthreads();
    select_bin(hist, part, kr3, &sh_bin, &sh_kr);
    const unsigned T = (B1 << 21) | (B2 << 10) | sh_bin;   // k-th largest key

    // ---- output pass: threshold, reconstruct original value, ballot mask
    float* __restrict__ orow = out + (size_t)row * F_COLS;
    const float* __restrict__ rb = g_rboost;
    const int lane = t & 31, w = t >> 5;
#pragma unroll 4
    for (int it = 0; it < 32; ++it) {
        int j = it * 256 + t;
        unsigned key = keys[j];
        unsigned bits = (key & 0x80000000u) ? (key & 0x7FFFFFFFu) : ~key;
        bool kept = key >= T;
        float val = kept ? __uint_as_float(bits) * rb[j] : 0.0f;
        orow[j] = val;
        unsigned bal = __ballot_sync(0xffffffffu, kept && key > 0x80000000u);
        if (lane == 0)
            g_mask[(size_t)(it * 8 + w) * N_ROWS + row] = bal;
    }
}

// ---------------------------------------------------------------------------
// Kernel 3: column counts via ballot bit-transpose, then EMA.
// Block b owns word-column b (columns 32b..32b+31). Warp wi covers 1024 rows.
// ---------------------------------------------------------------------------
__global__ __launch_bounds__(256)
void dc_kernel(const float* __restrict__ dc, float* __restrict__ dcout) {
    __shared__ unsigned s[256];
    const int t = threadIdx.x, lane = t & 31, wi = t >> 5;
    const int wc = blockIdx.x;
    const unsigned* __restrict__ mp = g_mask + (size_t)wc * N_ROWS;

    unsigned cnt = 0;
    const int r0 = wi * 1024;
    for (int g = 0; g < 32; ++g) {                 // 32 granules of 32 rows
        unsigned word = mp[r0 + g * 32 + lane];    // coalesced 128B
#pragma unroll
        for (int i = 0; i < 32; ++i) {
            unsigned bal = __ballot_sync(0xffffffffu, (word >> i) & 1u);
            if (lane == i) cnt += __popc(bal);
        }
    }
    s[t] = cnt;
    __syncthreads();
    if (t < 32) {
        unsigned tot = 0;
#pragma unroll
        for (int i = 0; i < 8; ++i) tot += s[i * 32 + t];
        int col = wc * 32 + t;
        dcout[col] = 0.9f * dc[col] + 0.1f * (float)tot;
    }
}

// ---------------------------------------------------------------------------
extern "C" void kernel_launch(void* const* d_in, const int* in_sizes, int n_in,
                              void* d_out, int out_size) {
    const float* inputs = (const float*)d_in[0];
    const float* dc     = (const float*)d_in[1];
    // defensive: metadata order is (inputs[N*F], duty_cycle[F])
    if (n_in >= 2 && in_sizes[0] < in_sizes[1]) {
        const float* tmp = inputs; inputs = dc; dc = tmp;
    }
    float* out = (float*)d_out;

    boost_kernel<<<(F_COLS + 255) / 256, 256>>>(dc);

    const int smem_bytes = (8192 + 2048 + 256) * 4;  // 41984 < 48KB default
    topk_kernel<<<N_ROWS, 256, smem_bytes>>>(inputs, out);

    if (out_size >= (int)((size_t)N_ROWS * F_COLS + F_COLS)) {
        float* dcout = out + (size_t)N_ROWS * F_COLS;
        dc_kernel<<<WORDS_PER_ROW, 256>>>(dc, dcout);
    }
}